// round 8
// baseline (speedup 1.0000x reference)
#include <cuda_runtime.h>
#include <math.h>

#define BATCH  4
#define NPTS   8192
#define TPB    256
#define RI     4                        // i's per thread
#define ITILE  64                       // i's per block (16 u-threads * RI)
#define ITILES (NPTS / ITILE)           // 128
#define JC     256                      // j's staged per chunk
#define JPT    (JC / 16)                // 16 j's per thread per chunk
#define CHUNKS (NPTS / JC)              // 32
#define SLOTS  (BATCH * NPTS)           // 32768
#define RBLK   128

// Column-min partials per i-tile (every slot written once per launch -> no init)
__device__ float g_colp[ITILES][SLOTS];   // 16.8 MB
__device__ float g_row[SLOTS];            // row mins are complete per block
__device__ float g_part[RBLK];

__global__ void __launch_bounds__(TPB) chamfer_fused(
    const float* __restrict__ pred, const float* __restrict__ gt)
{
    __shared__ float4 sg[JC];            // (-2gx,-2gy,-2gz,|g|^2)  4KB
    __shared__ float  cbuf[16][JC];      // per-u column mins       16KB

    int it = blockIdx.x % ITILES;
    int b  = blockIdx.x / ITILES;
    const float* P = pred + (size_t)b * 3 * NPTS;
    const float* G = gt   + (size_t)b * 3 * NPTS;

    int tid = threadIdx.x;
    int u = tid >> 4;        // 0..15  (i-group)
    int v = tid & 15;        // 0..15  (j-group) = lane bits [0:4)

    float px[RI], py[RI], pz[RI], psq[RI], rowmn[RI];
    #pragma unroll
    for (int p = 0; p < RI; p++) {
        int i = it * ITILE + u * RI + p;
        px[p] = P[i];
        py[p] = P[NPTS + i];
        pz[p] = P[2 * NPTS + i];
        psq[p] = fmaf(px[p], px[p], fmaf(py[p], py[p], pz[p] * pz[p]));
        rowmn[p] = 3.0e38f;
    }

    for (int ch = 0; ch < CHUNKS; ch++) {
        int jbase = ch * JC;
        __syncthreads();                       // sg/cbuf safe to overwrite
        {
            int j = jbase + tid;               // coalesced [3,N] reads
            float gx = G[j];
            float gy = G[NPTS + j];
            float gz = G[2 * NPTS + j];
            sg[tid] = make_float4(-2.0f * gx, -2.0f * gy, -2.0f * gz,
                                  fmaf(gx, gx, fmaf(gy, gy, gz * gz)));
        }
        __syncthreads();

        #pragma unroll 8
        for (int jj = 0; jj < JPT; jj++) {
            int js = v + jj * 16;              // <=2-way LDS conflict layout
            float4 g = sg[js];                 // LDS.128
            float cm = 3.0e38f;
            #pragma unroll
            for (int p = 0; p < RI; p++) {
                float d2 = fmaf(pz[p], g.z, g.w + psq[p]);
                d2 = fmaf(py[p], g.y, d2);
                d2 = fmaf(px[p], g.x, d2);
                rowmn[p] = fminf(rowmn[p], d2);
                cm = fminf(cm, d2);
            }
            cbuf[u][js] = cm;                  // plain STS, no atomics
        }
        __syncthreads();

        // column reduce across u: thread handles j = tid (one per thread)
        float m = cbuf[0][tid];
        #pragma unroll
        for (int u2 = 1; u2 < 16; u2++) m = fminf(m, cbuf[u2][tid]);
        g_colp[it][b * NPTS + jbase + tid] = m;
    }

    // Row mins: each thread only saw j's with js==v (mod 16) -> reduce across
    // the 16 v-threads of this u-group. v = lane bits [0:4), so xor 1/2/4/8
    // shuffles stay inside the group.
    #pragma unroll
    for (int p = 0; p < RI; p++) {
        float r = rowmn[p];
        #pragma unroll
        for (int mask = 8; mask >= 1; mask >>= 1)
            r = fminf(r, __shfl_xor_sync(0xffffffffu, r, mask));
        rowmn[p] = r;
    }
    if (v == 0) {
        #pragma unroll
        for (int p = 0; p < RI; p++)
            g_row[b * NPTS + it * ITILE + u * RI + p] = rowmn[p];
    }
}

__global__ void __launch_bounds__(TPB) reduce_kernel() {
    __shared__ float ssum[TPB];
    int gid = blockIdx.x * TPB + threadIdx.x;    // 32768 threads, one slot each

    float cm = 3.0e38f;
    #pragma unroll 16
    for (int t = 0; t < ITILES; t++) cm = fminf(cm, g_colp[t][gid]);

    float s = sqrtf(fmaxf(g_row[gid], 0.0f)) + sqrtf(fmaxf(cm, 0.0f));
    ssum[threadIdx.x] = s;
    __syncthreads();
    for (int off = TPB / 2; off > 0; off >>= 1) {
        if (threadIdx.x < off) ssum[threadIdx.x] += ssum[threadIdx.x + off];
        __syncthreads();
    }
    if (threadIdx.x == 0) g_part[blockIdx.x] = ssum[0];
}

__global__ void __launch_bounds__(RBLK) final_kernel(float* __restrict__ out) {
    __shared__ float ssum[RBLK];
    int tid = threadIdx.x;
    ssum[tid] = g_part[tid];
    __syncthreads();
    for (int off = RBLK / 2; off > 0; off >>= 1) {
        if (tid < off) ssum[tid] += ssum[tid + off];
        __syncthreads();
    }
    if (tid == 0) out[0] = ssum[0] * (1.0f / (float)BATCH);
}

extern "C" void kernel_launch(void* const* d_in, const int* in_sizes, int n_in,
                              void* d_out, int out_size) {
    const float* pred = (const float*)d_in[0];
    const float* gt   = (const float*)d_in[1];
    float* out = (float*)d_out;
    (void)in_sizes; (void)n_in; (void)out_size;

    // 128 i-tiles * 4 batches = 512 blocks; each scans all 8192 j once
    chamfer_fused<<<ITILES * BATCH, TPB>>>(pred, gt);
    reduce_kernel<<<RBLK, TPB>>>();
    final_kernel<<<1, RBLK>>>(out);
}

// round 9
// speedup vs baseline: 1.1961x; 1.1961x over previous
#include <cuda_runtime.h>
#include <math.h>

#define BATCH  4
#define NPTS   8192
#define TPB    256
#define RI     8                        // i's per thread
#define ITILE  128                      // 16 u-lanes * RI
#define ITILES (NPTS / ITILE)           // 64
#define JSPLIT 8
#define JRANGE (NPTS / JSPLIT)          // 1024 j's per block
#define JC     256                      // j's staged per chunk
#define NCH    (JRANGE / JC)            // 4
#define SLOTS  (BATCH * NPTS)           // 32768
#define RBLK   128

// Every slot written exactly once per launch -> no init kernel needed.
__device__ float g_colp[ITILES][SLOTS];   // 8.4 MB
__device__ float g_rowp[JSPLIT][SLOTS];   // 1 MB
__device__ float g_part[RBLK];

__global__ void __launch_bounds__(TPB) chamfer_fused(
    const float* __restrict__ pred, const float* __restrict__ gt)
{
    __shared__ float4 sg[JC];             // (-2gx,-2gy,-2gz,|g|^2)  4KB
    __shared__ float  rbuf[16][ITILE + 1];// row partials across v (padded)

    int bid = blockIdx.x;
    int it  = bid % ITILES;  bid /= ITILES;
    int jsp = bid % JSPLIT;  bid /= JSPLIT;
    int b   = bid;

    const float* P = pred + (size_t)b * 3 * NPTS;
    const float* G = gt   + (size_t)b * 3 * NPTS;

    int tid = threadIdx.x;
    int u = tid & 15;        // i-subgroup = lane bits [0:4)
    int v = tid >> 4;        // j-subgroup

    float px[RI], py[RI], pz[RI], psq[RI], rowmn[RI];
    #pragma unroll
    for (int p = 0; p < RI; p++) {
        int i = it * ITILE + p * 16 + u;
        px[p] = P[i];
        py[p] = P[NPTS + i];
        pz[p] = P[2 * NPTS + i];
        psq[p] = fmaf(px[p], px[p], fmaf(py[p], py[p], pz[p] * pz[p]));
        rowmn[p] = 3.0e38f;
    }

    int jbase0 = jsp * JRANGE;
    // prefetch chunk 0 (coalesced [3,N] reads, one j per thread)
    float gx = G[jbase0 + tid];
    float gy = G[NPTS + jbase0 + tid];
    float gz = G[2 * NPTS + jbase0 + tid];

    for (int ch = 0; ch < NCH; ch++) {
        int jbase = jbase0 + ch * JC;
        sg[tid] = make_float4(-2.0f * gx, -2.0f * gy, -2.0f * gz,
                              fmaf(gx, gx, fmaf(gy, gy, gz * gz)));
        __syncthreads();
        if (ch + 1 < NCH) {               // prefetch next chunk under compute
            int jn = jbase + JC + tid;
            gx = G[jn];
            gy = G[NPTS + jn];
            gz = G[2 * NPTS + jn];
        }

        #pragma unroll 8
        for (int jj = 0; jj < 16; jj++) {
            int js = v * 16 + jj;
            float4 g = sg[js];            // 2 distinct addrs/warp -> broadcast
            float d2[RI];
            #pragma unroll
            for (int p = 0; p < RI; p++) {
                float a = fmaf(pz[p], g.z, g.w + psq[p]);
                a = fmaf(py[p], g.y, a);
                a = fmaf(px[p], g.x, a);
                d2[p] = a;
                rowmn[p] = fminf(rowmn[p], a);
            }
            // column min over this thread's 8 i's (tree), then over 16 u-lanes
            float cm = fminf(fminf(fminf(d2[0], d2[1]), fminf(d2[2], d2[3])),
                             fminf(fminf(d2[4], d2[5]), fminf(d2[6], d2[7])));
            #pragma unroll
            for (int m = 8; m >= 1; m >>= 1)
                cm = fminf(cm, __shfl_xor_sync(0xffffffffu, cm, m));
            if (u == 0)
                g_colp[it][b * NPTS + jbase + js] = cm;   // unique writer
        }
        __syncthreads();                  // before overwriting sg
    }

    // Row mins: each thread saw only its v-subset of j -> reduce across 16 v
    #pragma unroll
    for (int p = 0; p < RI; p++)
        rbuf[v][p * 16 + u] = rowmn[p];
    __syncthreads();
    if (tid < ITILE) {
        float r = rbuf[0][tid];
        #pragma unroll
        for (int v2 = 1; v2 < 16; v2++) r = fminf(r, rbuf[v2][tid]);
        g_rowp[jsp][b * NPTS + it * ITILE + tid] = r;     // unique writer
    }
}

__global__ void __launch_bounds__(TPB) reduce_kernel() {
    __shared__ float ssum[TPB];
    int gid = blockIdx.x * TPB + threadIdx.x;   // 32768 threads, one slot each

    float cm = 3.0e38f;
    #pragma unroll 16
    for (int t = 0; t < ITILES; t++) cm = fminf(cm, g_colp[t][gid]);
    float rm = 3.0e38f;
    #pragma unroll
    for (int s = 0; s < JSPLIT; s++) rm = fminf(rm, g_rowp[s][gid]);

    float sv = sqrtf(fmaxf(rm, 0.0f)) + sqrtf(fmaxf(cm, 0.0f));
    ssum[threadIdx.x] = sv;
    __syncthreads();
    for (int off = TPB / 2; off > 0; off >>= 1) {
        if (threadIdx.x < off) ssum[threadIdx.x] += ssum[threadIdx.x + off];
        __syncthreads();
    }
    if (threadIdx.x == 0) g_part[blockIdx.x] = ssum[0];
}

__global__ void __launch_bounds__(RBLK) final_kernel(float* __restrict__ out) {
    __shared__ float ssum[RBLK];
    int tid = threadIdx.x;
    ssum[tid] = g_part[tid];
    __syncthreads();
    for (int off = RBLK / 2; off > 0; off >>= 1) {
        if (tid < off) ssum[tid] += ssum[tid + off];
        __syncthreads();
    }
    if (tid == 0) out[0] = ssum[0] * (1.0f / (float)BATCH);
}

extern "C" void kernel_launch(void* const* d_in, const int* in_sizes, int n_in,
                              void* d_out, int out_size) {
    const float* pred = (const float*)d_in[0];
    const float* gt   = (const float*)d_in[1];
    float* out = (float*)d_out;
    (void)in_sizes; (void)n_in; (void)out_size;

    // 64 i-tiles * 8 j-splits * 4 batches = 2048 blocks
    chamfer_fused<<<ITILES * JSPLIT * BATCH, TPB>>>(pred, gt);
    reduce_kernel<<<SLOTS / TPB, TPB>>>();   // 128 blocks
    final_kernel<<<1, RBLK>>>(out);
}

// round 10
// speedup vs baseline: 1.2545x; 1.0488x over previous
#include <cuda_runtime.h>
#include <math.h>

#define BATCH  4
#define NPTS   8192
#define TPB    256
#define RI     8                        // i's per thread
#define ITILE  128                      // 16 u-lanes * RI
#define ITILES (NPTS / ITILE)           // 64
#define JSPLIT 8
#define JRANGE (NPTS / JSPLIT)          // 1024 j's per block
#define JC     256                      // j's staged per chunk
#define NCH    (JRANGE / JC)            // 4
#define SLOTS  (BATCH * NPTS)           // 32768
#define RBLK   128

// Every slot written exactly once per launch -> no init kernel needed.
__device__ float g_colp[ITILES][SLOTS];   // 8.4 MB
__device__ float g_rowp[JSPLIT][SLOTS];   // 1 MB
__device__ float g_part[RBLK];

__global__ void __launch_bounds__(TPB, 4) chamfer_fused(
    const float* __restrict__ pred, const float* __restrict__ gt)
{
    __shared__ float4 sg[JC];             // (-2gx,-2gy,-2gz,|g|^2)  4KB
    __shared__ float  rbuf[16][ITILE + 1];// row partials across v (padded)

    int bid = blockIdx.x;
    int it  = bid % ITILES;  bid /= ITILES;
    int jsp = bid % JSPLIT;  bid /= JSPLIT;
    int b   = bid;

    const float* P = pred + (size_t)b * 3 * NPTS;
    const float* G = gt   + (size_t)b * 3 * NPTS;

    int tid = threadIdx.x;
    int u = tid & 15;        // i-subgroup = lane bits [0:4)
    int v = tid >> 4;        // j-subgroup

    float px[RI], py[RI], pz[RI], psq[RI], rowmn[RI];
    #pragma unroll
    for (int p = 0; p < RI; p++) {
        int i = it * ITILE + p * 16 + u;
        px[p] = P[i];
        py[p] = P[NPTS + i];
        pz[p] = P[2 * NPTS + i];
        psq[p] = fmaf(px[p], px[p], fmaf(py[p], py[p], pz[p] * pz[p]));
        rowmn[p] = 3.0e38f;
    }

    int jbase0 = jsp * JRANGE;
    // prefetch chunk 0 (coalesced [3,N] reads, one j per thread)
    float gx = G[jbase0 + tid];
    float gy = G[NPTS + jbase0 + tid];
    float gz = G[2 * NPTS + jbase0 + tid];

    for (int ch = 0; ch < NCH; ch++) {
        int jbase = jbase0 + ch * JC;
        sg[tid] = make_float4(-2.0f * gx, -2.0f * gy, -2.0f * gz,
                              fmaf(gx, gx, fmaf(gy, gy, gz * gz)));
        __syncthreads();
        if (ch + 1 < NCH) {               // prefetch next chunk under compute
            int jn = jbase + JC + tid;
            gx = G[jn];
            gy = G[NPTS + jn];
            gz = G[2 * NPTS + jn];
        }

        #pragma unroll 8
        for (int jj = 0; jj < 16; jj++) {
            int js = v * 16 + jj;
            float4 g = sg[js];            // 2 distinct addrs/warp -> broadcast
            float cm = 3.0e38f;
            #pragma unroll
            for (int p = 0; p < RI; p++) {
                float a = fmaf(pz[p], g.z, g.w + psq[p]);
                a = fmaf(py[p], g.y, a);
                a = fmaf(px[p], g.x, a);
                rowmn[p] = fminf(rowmn[p], a);
                cm = fminf(cm, a);        // consume immediately (no d2[] array)
            }
            // column min over 16 u-lanes (lane bits 0-3)
            #pragma unroll
            for (int m = 8; m >= 1; m >>= 1)
                cm = fminf(cm, __shfl_xor_sync(0xffffffffu, cm, m));
            if (u == 0)
                g_colp[it][b * NPTS + jbase + js] = cm;   // unique writer
        }
        __syncthreads();                  // before overwriting sg
    }

    // Row mins: each thread saw only its v-subset of j -> reduce across 16 v
    #pragma unroll
    for (int p = 0; p < RI; p++)
        rbuf[v][p * 16 + u] = rowmn[p];
    __syncthreads();
    if (tid < ITILE) {
        float r = rbuf[0][tid];
        #pragma unroll
        for (int v2 = 1; v2 < 16; v2++) r = fminf(r, rbuf[v2][tid]);
        g_rowp[jsp][b * NPTS + it * ITILE + tid] = r;     // unique writer
    }
}

__global__ void __launch_bounds__(TPB) reduce_kernel() {
    __shared__ float ssum[TPB];
    int gid = blockIdx.x * TPB + threadIdx.x;   // 32768 threads, one slot each

    float cm = 3.0e38f;
    #pragma unroll 16
    for (int t = 0; t < ITILES; t++) cm = fminf(cm, g_colp[t][gid]);
    float rm = 3.0e38f;
    #pragma unroll
    for (int s = 0; s < JSPLIT; s++) rm = fminf(rm, g_rowp[s][gid]);

    float sv = sqrtf(fmaxf(rm, 0.0f)) + sqrtf(fmaxf(cm, 0.0f));
    ssum[threadIdx.x] = sv;
    __syncthreads();
    for (int off = TPB / 2; off > 0; off >>= 1) {
        if (threadIdx.x < off) ssum[threadIdx.x] += ssum[threadIdx.x + off];
        __syncthreads();
    }
    if (threadIdx.x == 0) g_part[blockIdx.x] = ssum[0];
}

__global__ void __launch_bounds__(RBLK) final_kernel(float* __restrict__ out) {
    __shared__ float ssum[RBLK];
    int tid = threadIdx.x;
    ssum[tid] = g_part[tid];
    __syncthreads();
    for (int off = RBLK / 2; off > 0; off >>= 1) {
        if (tid < off) ssum[tid] += ssum[tid + off];
        __syncthreads();
    }
    if (tid == 0) out[0] = ssum[0] * (1.0f / (float)BATCH);
}

extern "C" void kernel_launch(void* const* d_in, const int* in_sizes, int n_in,
                              void* d_out, int out_size) {
    const float* pred = (const float*)d_in[0];
    const float* gt   = (const float*)d_in[1];
    float* out = (float*)d_out;
    (void)in_sizes; (void)n_in; (void)out_size;

    // 64 i-tiles * 8 j-splits * 4 batches = 2048 blocks
    chamfer_fused<<<ITILES * JSPLIT * BATCH, TPB>>>(pred, gt);
    reduce_kernel<<<SLOTS / TPB, TPB>>>();   // 128 blocks
    final_kernel<<<1, RBLK>>>(out);
}

// round 11
// speedup vs baseline: 1.4274x; 1.1378x over previous
#include <cuda_runtime.h>
#include <math.h>

#define BATCH  4
#define NPTS   8192
#define TPB    256
#define RI     8                        // i's per thread
#define ITILE  128                      // 16 u-lanes * RI
#define ITILES (NPTS / ITILE)           // 64
#define JSPLIT 8
#define JRANGE (NPTS / JSPLIT)          // 1024 j's per block
#define JC     256                      // j's staged per chunk
#define NCH    (JRANGE / JC)            // 4
#define SLOTS  (BATCH * NPTS)           // 32768
#define RBLK   128

// Every slot written exactly once per launch -> no init kernel needed.
__device__ float g_colp[ITILES][SLOTS];   // 8.4 MB
__device__ float g_rowp[JSPLIT][SLOTS];   // 1 MB
__device__ float g_part[RBLK];

__global__ void __launch_bounds__(TPB, 4) chamfer_fused(
    const float* __restrict__ pred, const float* __restrict__ gt)
{
    __shared__ float4 sg[JC];             // (-2gx,-2gy,-2gz,|g|^2)   4KB
    __shared__ float  cbuf[JC][17];       // col candidates [j][u]    17KB (pad 17)
    __shared__ float  rbuf[16][ITILE + 1];// row partials across v

    int bid = blockIdx.x;
    int it  = bid % ITILES;  bid /= ITILES;
    int jsp = bid % JSPLIT;  bid /= JSPLIT;
    int b   = bid;

    const float* P = pred + (size_t)b * 3 * NPTS;
    const float* G = gt   + (size_t)b * 3 * NPTS;

    int tid = threadIdx.x;
    int u = tid & 15;        // i-subgroup = lane bits [0:4)
    int v = tid >> 4;        // j-subgroup

    float px[RI], py[RI], pz[RI], psq[RI], rowmn[RI];
    #pragma unroll
    for (int p = 0; p < RI; p++) {
        int i = it * ITILE + p * 16 + u;
        px[p] = P[i];
        py[p] = P[NPTS + i];
        pz[p] = P[2 * NPTS + i];
        psq[p] = fmaf(px[p], px[p], fmaf(py[p], py[p], pz[p] * pz[p]));
        rowmn[p] = 3.0e38f;
    }

    int jbase0 = jsp * JRANGE;
    // prefetch chunk 0 (coalesced [3,N] reads, one j per thread)
    float gx = G[jbase0 + tid];
    float gy = G[NPTS + jbase0 + tid];
    float gz = G[2 * NPTS + jbase0 + tid];

    for (int ch = 0; ch < NCH; ch++) {
        int jbase = jbase0 + ch * JC;
        sg[tid] = make_float4(-2.0f * gx, -2.0f * gy, -2.0f * gz,
                              fmaf(gx, gx, fmaf(gy, gy, gz * gz)));
        __syncthreads();                  // sg ready; prev finalize done
        if (ch + 1 < NCH) {               // prefetch next chunk under compute
            int jn = jbase + JC + tid;
            gx = G[jn];
            gy = G[NPTS + jn];
            gz = G[2 * NPTS + jn];
        }

        #pragma unroll
        for (int jj = 0; jj < 16; jj++) {
            int js = v * 16 + jj;
            float4 g = sg[js];            // 2 distinct addrs/warp -> broadcast
            float cm = 3.0e38f;
            #pragma unroll
            for (int p = 0; p < RI; p++) {
                float a = fmaf(pz[p], g.z, g.w + psq[p]);
                a = fmaf(py[p], g.y, a);
                a = fmaf(px[p], g.x, a);
                rowmn[p] = fminf(rowmn[p], a);
                cm = fminf(cm, a);
            }
            cbuf[js][u] = cm;             // conflict-free STS (stride 17)
        }
        __syncthreads();                  // all candidates in cbuf

        // column finalize: thread tid owns j = jbase + tid
        float m = cbuf[tid][0];
        #pragma unroll
        for (int u2 = 1; u2 < 16; u2++) m = fminf(m, cbuf[tid][u2]);
        g_colp[it][b * NPTS + jbase + tid] = m;   // coalesced unique writer
    }

    // Row mins: each thread saw only its v-subset of j -> reduce across 16 v
    __syncthreads();
    #pragma unroll
    for (int p = 0; p < RI; p++)
        rbuf[v][p * 16 + u] = rowmn[p];
    __syncthreads();
    if (tid < ITILE) {
        float r = rbuf[0][tid];
        #pragma unroll
        for (int v2 = 1; v2 < 16; v2++) r = fminf(r, rbuf[v2][tid]);
        g_rowp[jsp][b * NPTS + it * ITILE + tid] = r;     // unique writer
    }
}

__global__ void __launch_bounds__(TPB) reduce_kernel() {
    __shared__ float ssum[TPB];
    int gid = blockIdx.x * TPB + threadIdx.x;   // 32768 threads, one slot each

    float cm = 3.0e38f;
    #pragma unroll 16
    for (int t = 0; t < ITILES; t++) cm = fminf(cm, g_colp[t][gid]);
    float rm = 3.0e38f;
    #pragma unroll
    for (int s = 0; s < JSPLIT; s++) rm = fminf(rm, g_rowp[s][gid]);

    float sv = sqrtf(fmaxf(rm, 0.0f)) + sqrtf(fmaxf(cm, 0.0f));
    ssum[threadIdx.x] = sv;
    __syncthreads();
    for (int off = TPB / 2; off > 0; off >>= 1) {
        if (threadIdx.x < off) ssum[threadIdx.x] += ssum[threadIdx.x + off];
        __syncthreads();
    }
    if (threadIdx.x == 0) g_part[blockIdx.x] = ssum[0];
}

__global__ void __launch_bounds__(RBLK) final_kernel(float* __restrict__ out) {
    __shared__ float ssum[RBLK];
    int tid = threadIdx.x;
    ssum[tid] = g_part[tid];
    __syncthreads();
    for (int off = RBLK / 2; off > 0; off >>= 1) {
        if (tid < off) ssum[tid] += ssum[tid + off];
        __syncthreads();
    }
    if (tid == 0) out[0] = ssum[0] * (1.0f / (float)BATCH);
}

extern "C" void kernel_launch(void* const* d_in, const int* in_sizes, int n_in,
                              void* d_out, int out_size) {
    const float* pred = (const float*)d_in[0];
    const float* gt   = (const float*)d_in[1];
    float* out = (float*)d_out;
    (void)in_sizes; (void)n_in; (void)out_size;

    // 64 i-tiles * 8 j-splits * 4 batches = 2048 blocks
    chamfer_fused<<<ITILES * JSPLIT * BATCH, TPB>>>(pred, gt);
    reduce_kernel<<<SLOTS / TPB, TPB>>>();   // 128 blocks
    final_kernel<<<1, RBLK>>>(out);
}